// round 5
// baseline (speedup 1.0000x reference)
#include <cuda_runtime.h>
#include <cuda_bf16.h>
#include <math.h>

#define NFR    65536
#define DIM    512
#define HEADS  8
#define ATTR   256
#define XDIM   768
#define KSTEPS 16
#define SCALE  0.125f
#define GRIDW  296

// ------------------------- static device scratch -------------------------
__device__ __align__(16) __nv_bfloat16 g_Fh [NFR*DIM];   // row-major bf16 frames
__device__ __align__(16) __nv_bfloat16 g_FhT[DIM*NFR];   // transposed bf16 frames
__device__ __align__(16) float g_WckT[DIM*DIM];          // scale*(W_ctx@Wk)^T [o][i]
__device__ __align__(16) float g_Wcv [DIM*DIM];          // W_ctx@Wv [i][o]
__device__ __align__(16) float g_Wih2[1536*XDIM];        // [W_ih[:,:256] | W_ih[:,256:]@Wo^T]
__device__ __align__(16) float g_bih2[1536];
__device__ __align__(16) float g_cvec[HEADS*DIM];
__device__ __align__(16) float g_bvp[DIM];
__device__ __align__(16) float g_bo2[DIM];
__device__ __align__(16) float g_colsum[DIM];
__device__ __align__(16) float g_h[2][DIM];
__device__ __align__(16) float g_u[HEADS*DIM];           // [h][i]
__device__ __align__(16) float g_x[XDIM];                // [a_prev(256); vraw(512)]
__device__ __align__(16) float g_ihh[3072];
__device__ __align__(16) float g_la[NFR*HEADS];          // logits [n][h] fp32
__device__ __align__(16) float g_wpart[GRIDW*4096];
__device__ float    g_spart[GRIDW*HEADS];
__device__ unsigned g_maxbits[HEADS];

__device__ __forceinline__ unsigned encf(float f){
    unsigned u = __float_as_uint(f);
    return (u & 0x80000000u) ? ~u : (u | 0x80000000u);
}
__device__ __forceinline__ float decf(unsigned e){
    unsigned u = (e & 0x80000000u) ? (e ^ 0x80000000u) : ~e;
    return __uint_as_float(u);
}
__device__ __forceinline__ float wred(float a){
    #pragma unroll
    for (int o = 16; o; o >>= 1) a += __shfl_xor_sync(0xffffffffu, a, o);
    return a;
}
// ---- packed fp32 (fma.rn.f32x2) helpers ----
#define FMA2(d,a,b) asm("fma.rn.f32x2 %0, %1, %2, %0;" : "+l"(d) : "l"(a), "l"(b))
__device__ __forceinline__ unsigned long long fpack(float a, float b){
    unsigned long long r;
    asm("mov.b64 %0, {%1, %2};" : "=l"(r) : "f"(a), "f"(b));
    return r;
}
__device__ __forceinline__ unsigned long long bfp(unsigned w){
    // bf16x2 word -> packed (lo, hi) fp32 pair
    unsigned lo = w << 16, hi = w & 0xffff0000u;
    unsigned long long r;
    asm("mov.b64 %0, {%1, %2};" : "=l"(r) : "r"(lo), "r"(hi));
    return r;
}
__device__ __forceinline__ float2 funp(unsigned long long v){
    float x, y;
    asm("mov.b64 {%0, %1}, %2;" : "=f"(x), "=f"(y) : "l"(v));
    return make_float2(x, y);
}

// ------------------------------ setup ------------------------------------
__global__ void p0_zero(){ g_colsum[threadIdx.x] = 0.0f; }

// F -> bf16 row-major + column sums
__global__ void p1c(const float4* __restrict__ F4){
    int t = threadIdx.x;                      // 128 threads = 128 float4 cols
    float4 acc = make_float4(0.f,0.f,0.f,0.f);
    size_t r0 = (size_t)blockIdx.x * (NFR/128);
    uint2* out = (uint2*)g_Fh;
    for (int r = 0; r < NFR/128; r++){
        size_t row = r0 + r;
        float4 f = F4[row*128 + t];
        acc.x += f.x; acc.y += f.y; acc.z += f.z; acc.w += f.w;
        uint2 pk;
        pk.x = ((unsigned)__bfloat16_as_ushort(__float2bfloat16_rn(f.y)) << 16)
             |  (unsigned)__bfloat16_as_ushort(__float2bfloat16_rn(f.x));
        pk.y = ((unsigned)__bfloat16_as_ushort(__float2bfloat16_rn(f.w)) << 16)
             |  (unsigned)__bfloat16_as_ushort(__float2bfloat16_rn(f.z));
        out[row*128 + t] = pk;
    }
    atomicAdd(&g_colsum[t*4+0], acc.x);
    atomicAdd(&g_colsum[t*4+1], acc.y);
    atomicAdd(&g_colsum[t*4+2], acc.z);
    atomicAdd(&g_colsum[t*4+3], acc.w);
}

// transpose g_Fh -> g_FhT, 64x64 tiles
__global__ void p1t(){
    __shared__ unsigned short ts[64][72];
    const int tid = threadIdx.x;
    const int n0 = blockIdx.x*64, k0 = blockIdx.y*64;
    #pragma unroll
    for (int it = 0; it < 2; it++){
        int e = tid + it*256, r = e >> 3, c = e & 7;
        uint4 v = *(const uint4*)(g_Fh + (size_t)(n0+r)*DIM + k0 + c*8);
        *(uint4*)&ts[r][c*8] = v;
    }
    __syncthreads();
    #pragma unroll
    for (int it = 0; it < 2; it++){
        int e = tid + it*256, kk = e >> 3, cn = e & 7;
        unsigned w0 = (unsigned)ts[cn*8+0][kk] | ((unsigned)ts[cn*8+1][kk] << 16);
        unsigned w1 = (unsigned)ts[cn*8+2][kk] | ((unsigned)ts[cn*8+3][kk] << 16);
        unsigned w2 = (unsigned)ts[cn*8+4][kk] | ((unsigned)ts[cn*8+5][kk] << 16);
        unsigned w3 = (unsigned)ts[cn*8+6][kk] | ((unsigned)ts[cn*8+7][kk] << 16);
        uint4 v = make_uint4(w0,w1,w2,w3);
        *(uint4*)(g_FhT + (size_t)(k0+kk)*NFR + n0 + cn*8) = v;
    }
}

// z=0: WckT = scale*(W_ctx@Wk)^T ; z=1: Wcv = W_ctx@Wv
__global__ void p2_gemm(const float* __restrict__ Wctx,
                        const float* __restrict__ Wk,
                        const float* __restrict__ Wv){
    __shared__ float sA[32][33];
    __shared__ float sB[32][33];
    int tx = threadIdx.x, ty = threadIdx.y;
    const float* B = blockIdx.z ? Wv : Wk;
    int i0 = blockIdx.y*32, j0 = blockIdx.x*32;
    float acc[4] = {0.f,0.f,0.f,0.f};
    for (int m0 = 0; m0 < DIM; m0 += 32){
        #pragma unroll
        for (int k = 0; k < 4; k++){
            sA[ty+8*k][tx] = Wctx[(size_t)(i0+ty+8*k)*DIM + m0+tx];
            sB[ty+8*k][tx] = B[(size_t)(m0+ty+8*k)*DIM + j0+tx];
        }
        __syncthreads();
        #pragma unroll
        for (int mm = 0; mm < 32; mm++){
            float b = sB[mm][tx];
            #pragma unroll
            for (int k = 0; k < 4; k++) acc[k] += sA[ty+8*k][mm]*b;
        }
        __syncthreads();
    }
    if (blockIdx.z){
        #pragma unroll
        for (int k = 0; k < 4; k++)
            g_Wcv[(size_t)(i0+ty+8*k)*DIM + j0+tx] = acc[k];
    } else {
        __syncthreads();
        #pragma unroll
        for (int k = 0; k < 4; k++) sA[tx][ty+8*k] = acc[k];
        __syncthreads();
        #pragma unroll
        for (int k = 0; k < 4; k++)
            g_WckT[(size_t)(j0+ty+8*k)*DIM + i0+tx] = SCALE*sA[ty+8*k][tx];
    }
}

// Wih2: x<8 -> gemm tile (W_ih[:,256:]@Wo^T) ; x>=8 -> copy W_ih[:, :256]
__global__ void __launch_bounds__(256) p3_wih(const float* __restrict__ W_ih,
                                              const float* __restrict__ Wo){
    const int tid = threadIdx.x;
    const int i0 = blockIdx.y*64;
    if (blockIdx.x < 8){
        __shared__ float sA[64][33];
        __shared__ float sB[64][33];
        const int j0 = blockIdx.x*64;
        const int tx = tid & 15, ty = tid >> 4;
        float acc[4][4];
        #pragma unroll
        for (int a = 0; a < 4; a++)
            #pragma unroll
            for (int b = 0; b < 4; b++) acc[a][b] = 0.f;
        for (int m0 = 0; m0 < DIM; m0 += 32){
            #pragma unroll
            for (int q = 0; q < 2; q++){
                int e = tid + q*256, r = e >> 3, c = e & 7;
                float4 va = *(const float4*)(W_ih + (size_t)(i0+r)*XDIM + 256 + m0 + c*4);
                sA[r][c*4+0]=va.x; sA[r][c*4+1]=va.y; sA[r][c*4+2]=va.z; sA[r][c*4+3]=va.w;
                float4 vb = *(const float4*)(Wo + (size_t)(j0+r)*DIM + m0 + c*4);
                sB[r][c*4+0]=vb.x; sB[r][c*4+1]=vb.y; sB[r][c*4+2]=vb.z; sB[r][c*4+3]=vb.w;
            }
            __syncthreads();
            #pragma unroll
            for (int m = 0; m < 32; m++){
                float a4[4], b4[4];
                #pragma unroll
                for (int k = 0; k < 4; k++){ a4[k] = sA[ty*4+k][m]; b4[k] = sB[tx*4+k][m]; }
                #pragma unroll
                for (int a = 0; a < 4; a++)
                    #pragma unroll
                    for (int b = 0; b < 4; b++) acc[a][b] += a4[a]*b4[b];
            }
            __syncthreads();
        }
        #pragma unroll
        for (int a = 0; a < 4; a++){
            float4 v = make_float4(acc[a][0], acc[a][1], acc[a][2], acc[a][3]);
            *(float4*)(g_Wih2 + (size_t)(i0+ty*4+a)*XDIM + 256 + j0 + tx*4) = v;
        }
    } else {
        const int c0 = (blockIdx.x-8)*64;
        for (int e = tid; e < 64*16; e += 256){
            int r = e >> 4, c = e & 15;
            *(float4*)(g_Wih2 + (size_t)(i0+r)*XDIM + c0 + c*4) =
                *(const float4*)(W_ih + (size_t)(i0+r)*XDIM + c0 + c*4);
        }
    }
}

// bvp = bctx@Wv + bv
__global__ void p4a(const float* __restrict__ bctx, const float* __restrict__ Wv,
                    const float* __restrict__ bv){
    __shared__ float sp[4][64];
    const int tid = threadIdx.x, tc = tid & 63, kc = tid >> 6;
    const int t = blockIdx.x*64 + tc;
    float a = 0.f;
    for (int k = kc*128; k < kc*128+128; k++) a += bctx[k]*Wv[(size_t)k*DIM + t];
    sp[kc][tc] = a;
    __syncthreads();
    if (tid < 64)
        g_bvp[blockIdx.x*64+tid] = sp[0][tid]+sp[1][tid]+sp[2][tid]+sp[3][tid]
                                   + bv[blockIdx.x*64+tid];
}

// bo2 = bvp@Wo + bo
__global__ void p4b(const float* __restrict__ Wo, const float* __restrict__ bo){
    __shared__ float sp[4][64];
    const int tid = threadIdx.x, tc = tid & 63, kc = tid >> 6;
    const int t = blockIdx.x*64 + tc;
    float a = 0.f;
    for (int k = kc*128; k < kc*128+128; k++) a += g_bvp[k]*Wo[(size_t)k*DIM + t];
    sp[kc][tc] = a;
    __syncthreads();
    if (tid < 64)
        g_bo2[blockIdx.x*64+tid] = sp[0][tid]+sp[1][tid]+sp[2][tid]+sp[3][tid]
                                   + bo[blockIdx.x*64+tid];
}

// bih2 = b_ih + W_ih[:,256:]@bo2 ; also copy start token into g_x
__global__ void p4c(const float* __restrict__ W_ih, const float* __restrict__ b_ih,
                    const float* __restrict__ start){
    const int tid = threadIdx.x, warp = tid >> 5, lane = tid & 31;
    const int gw = blockIdx.x*8 + warp;
    for (int r = gw; r < 1536; r += 192){
        const float4* W = (const float4*)(W_ih + (size_t)r*XDIM + 256);
        const float4* B = (const float4*)g_bo2;
        float a = 0.f;
        #pragma unroll
        for (int k = 0; k < 4; k++){
            float4 w = W[lane + 32*k], x = B[lane + 32*k];
            a += w.x*x.x + w.y*x.y + w.z*x.z + w.w*x.w;
        }
        a = wred(a);
        if (lane == 0) g_bih2[r] = a + b_ih[r];
    }
    if (blockIdx.x == 0 && tid < ATTR) g_x[tid] = start[tid];
}

// h0 (blocks 0..7) + cvec (blocks 8..15)
__global__ void p4d(const float* __restrict__ Wctx, const float* __restrict__ bctx,
                    const float* __restrict__ bq){
    __shared__ float sp[4][64];
    const int tid = threadIdx.x, b = blockIdx.x;
    if (b < 8){
        const int tc = tid & 63, kc = tid >> 6;
        const int t = b*64 + tc;
        float a = 0.f;
        for (int k = kc*128; k < kc*128+128; k++) a += g_colsum[k]*Wctx[(size_t)k*DIM + t];
        sp[kc][tc] = a;
        __syncthreads();
        if (tid < 64)
            g_h[0][b*64+tid] = (sp[0][tid]+sp[1][tid]+sp[2][tid]+sp[3][tid])*(1.0f/(float)NFR)
                               + bctx[b*64+tid];
    } else {
        const int b2 = b - 8;
        #pragma unroll
        for (int rr = 0; rr < 2; rr++){
            int r = b2*512 + rr*256 + tid;
            int h = r >> 9, i = r & 511;
            float s = 0.f;
            #pragma unroll 8
            for (int d = 0; d < 64; d++)
                s += g_WckT[(size_t)(h*64+d)*DIM + i]*bq[h*64+d];
            g_cvec[r] = s;
        }
    }
}

// ----------------------------- per-step ----------------------------------
// block h: q_h = Wq_h^T@h ; u_h = WckT_h@q_h + cvec_h ; zero vraw slice + maxbits
__global__ void s1_u(const float* __restrict__ Wq, int p){
    __shared__ float spq[4][64];
    __shared__ float sq[64];
    const int h = blockIdx.x, tid = threadIdx.x;
    if (tid < 64) g_x[256 + h*64 + tid] = 0.f;
    if (h == 0 && tid < 8) g_maxbits[tid] = 0u;
    const int d = tid & 63, ic = tid >> 6;
    float a = 0.f;
    #pragma unroll 4
    for (int ii = 0; ii < 128; ii++){
        int i = ic*128 + ii;
        a += g_h[p][i] * Wq[(size_t)i*DIM + h*64 + d];
    }
    spq[ic][d] = a;
    __syncthreads();
    if (tid < 64) sq[tid] = spq[0][tid]+spq[1][tid]+spq[2][tid]+spq[3][tid];
    __syncthreads();
    for (int i = tid; i < DIM; i += 256){
        float acc = g_cvec[h*DIM + i];
        #pragma unroll 8
        for (int dd = 0; dd < 64; dd++)
            acc += sq[dd]*g_WckT[(size_t)(h*64+dd)*DIM + i];
        g_u[h*DIM + i] = acc;
    }
}

// logits: thread handles adjacent row-pair via transposed F; exact global max via atomicMax
__global__ void __launch_bounds__(256) sL(){
    __shared__ float su[512][8];          // su[k][h]
    __shared__ unsigned sbm[8];
    const int tid = threadIdx.x;
    if (tid < 8) sbm[tid] = 0u;
    for (int i = tid; i < 4096; i += 256){
        int k = i >> 3, h = i & 7;
        su[k][h] = g_u[h*512 + k];
    }
    __syncthreads();
    const int pidx = blockIdx.x*256 + tid;              // row pair index
    const unsigned* Fc = (const unsigned*)g_FhT;        // [k][n/2] bf16x2
    unsigned long long la[4] = {0,0,0,0};               // row0: (l0,l1)(l2,l3)(l4,l5)(l6,l7)
    unsigned long long lb[4] = {0,0,0,0};               // row1
    #pragma unroll 4
    for (int k = 0; k < 512; k++){
        unsigned w = Fc[(size_t)k*(NFR/2) + pidx];
        unsigned long long faa = fpack(__uint_as_float(w << 16), __uint_as_float(w << 16));
        unsigned long long fbb = fpack(__uint_as_float(w & 0xffff0000u),
                                       __uint_as_float(w & 0xffff0000u));
        const ulonglong2* up = (const ulonglong2*)&su[k][0];
        ulonglong2 u0 = up[0], u1 = up[1];
        FMA2(la[0], faa, u0.x); FMA2(la[1], faa, u0.y);
        FMA2(la[2], faa, u1.x); FMA2(la[3], faa, u1.y);
        FMA2(lb[0], fbb, u0.x); FMA2(lb[1], fbb, u0.y);
        FMA2(lb[2], fbb, u1.x); FMA2(lb[3], fbb, u1.y);
    }
    float l0[8], l1[8];
    #pragma unroll
    for (int j = 0; j < 4; j++){
        float2 a = funp(la[j]); l0[2*j] = a.x; l0[2*j+1] = a.y;
        float2 b = funp(lb[j]); l1[2*j] = b.x; l1[2*j+1] = b.y;
    }
    const size_t n0 = (size_t)pidx*2;
    float4* Lp = (float4*)(g_la + n0*8);
    Lp[0] = make_float4(l0[0],l0[1],l0[2],l0[3]);
    Lp[1] = make_float4(l0[4],l0[5],l0[6],l0[7]);
    Lp[2] = make_float4(l1[0],l1[1],l1[2],l1[3]);
    Lp[3] = make_float4(l1[4],l1[5],l1[6],l1[7]);
    // per-head max
    float m8[8];
    #pragma unroll
    for (int h = 0; h < 8; h++){
        float m = fmaxf(l0[h], l1[h]);
        #pragma unroll
        for (int o = 16; o; o >>= 1) m = fmaxf(m, __shfl_xor_sync(0xffffffffu, m, o));
        m8[h] = m;
    }
    if ((tid & 31) == 0){
        #pragma unroll
        for (int h = 0; h < 8; h++) atomicMax(&sbm[h], encf(m8[h]));
    }
    __syncthreads();
    if (tid < 8) atomicMax(&g_maxbits[tid], sbm[tid]);
}

// weighted frame sums: w[h][:] = sum_n exp(L-M)*F[n][:], + sumexp partials
__global__ void __launch_bounds__(256,2) sW(){
    const int tid = threadIdx.x, warp = tid >> 5, lane = tid & 31;
    const int half = warp & 1;
    const int stream = blockIdx.x*4 + (warp >> 1);
    const float Mh = decf(g_maxbits[lane & 7]);
    unsigned long long acc[8][4];
    #pragma unroll
    for (int h = 0; h < 8; h++)
        #pragma unroll
        for (int j = 0; j < 4; j++) acc[h][j] = 0ull;
    float ssum = 0.f;
    const uint4* F16 = (const uint4*)g_Fh;
    for (int n = stream; n < NFR; n += GRIDW*4){
        uint4 fv = F16[(size_t)n*64 + half*32 + lane];
        float e = __expf(g_la[(size_t)n*8 + (lane & 7)] - Mh);
        if (half == 0 && lane < 8) ssum += e;
        unsigned long long f0 = bfp(fv.x), f1 = bfp(fv.y), f2 = bfp(fv.z), f3 = bfp(fv.w);
        #pragma unroll
        for (int h = 0; h < 8; h++){
            float eh = __shfl_sync(0xffffffffu, e, h);
            unsigned long long ee = fpack(eh, eh);
            FMA2(acc[h][0], ee, f0); FMA2(acc[h][1], ee, f1);
            FMA2(acc[h][2], ee, f2); FMA2(acc[h][3], ee, f3);
        }
    }
    __shared__ float sw[8][512];
    __shared__ float ss[8];
    for (int i = tid; i < 4096; i += 256) ((float*)sw)[i] = 0.f;
    if (tid < 8) ss[tid] = 0.f;
    __syncthreads();
    const int cbase = half*256 + lane*8;
    #pragma unroll
    for (int h = 0; h < 8; h++)
        #pragma unroll
        for (int j = 0; j < 4; j++){
            float2 v = funp(acc[h][j]);
            atomicAdd(&sw[h][cbase + j*2 + 0], v.x);
            atomicAdd(&sw[h][cbase + j*2 + 1], v.y);
        }
    if (half == 0 && lane < 8) atomicAdd(&ss[lane], ssum);
    __syncthreads();
    float* op = g_wpart + (size_t)blockIdx.x*4096;
    for (int i = tid; i < 4096; i += 256) op[i] = ((float*)sw)[i];
    if (tid < 8) g_spart[blockIdx.x*8 + tid] = ss[tid];
}

// combine partials -> c ; vraw += c@Wcv (into g_x[256:768])
__global__ void s3c(){
    __shared__ float sS[8];
    __shared__ float sc[256];
    __shared__ float sv[4][64];
    const int tid = threadIdx.x, bi = blockIdx.x;
    if (tid < 8){
        float S = 0.f;
        for (int b = 0; b < GRIDW; b++) S += g_spart[b*8 + tid];
        sS[tid] = S;
    }
    __syncthreads();
    const int idx = bi*256 + tid;
    const int hb = bi >> 1;
    {
        float a = 0.f;
        #pragma unroll 4
        for (int b = 0; b < GRIDW; b++) a += g_wpart[(size_t)b*4096 + idx];
        sc[tid] = a / sS[hb];
    }
    __syncthreads();
    const int d = tid & 63, isub = tid >> 6;
    const int i0 = (bi & 1)*256;
    float pv = 0.f;
    #pragma unroll 8
    for (int ii = 0; ii < 64; ii++){
        int i = i0 + isub*64 + ii;
        pv += sc[isub*64+ii]*g_Wcv[(size_t)i*DIM + hb*64 + d];
    }
    sv[isub][d] = pv;
    __syncthreads();
    if (tid < 64)
        atomicAdd(&g_x[256 + hb*64 + tid],
                  sv[0][tid]+sv[1][tid]+sv[2][tid]+sv[3][tid]);
}

// GRU matvecs
__global__ void s5_gru(const float* __restrict__ W_hh, int p){
    const int warp = threadIdx.x >> 5, lane = threadIdx.x & 31;
    const int gw = blockIdx.x*8 + warp, nw = gridDim.x*8;
    for (int r = gw; r < 3072; r += nw){
        float a = 0.f;
        if (r < 1536){
            const float4* W = (const float4*)(g_Wih2 + (size_t)r*XDIM);
            const float4* X = (const float4*)g_x;
            #pragma unroll
            for (int k = 0; k < 6; k++){
                float4 w = W[lane + 32*k], x = X[lane + 32*k];
                a += w.x*x.x + w.y*x.y + w.z*x.z + w.w*x.w;
            }
            a = wred(a);
            if (lane == 0) g_ihh[r] = a + g_bih2[r];
        } else {
            int rr = r - 1536;
            const float4* W = (const float4*)(W_hh + (size_t)rr*DIM);
            const float4* H = (const float4*)g_h[p];
            #pragma unroll
            for (int k = 0; k < 4; k++){
                float4 w = W[lane + 32*k], h = H[lane + 32*k];
                a += w.x*h.x + w.y*h.y + w.z*h.z + w.w*h.w;
            }
            a = wred(a);
            if (lane == 0) g_ihh[r] = a;
        }
    }
}

// gates + heads + output
__global__ void s6_fin(int p, int step, float* __restrict__ out,
                       const float* __restrict__ b_hn,
                       const float* __restrict__ W_attr, const float* __restrict__ b_attr,
                       const float* __restrict__ W_conf, const float* __restrict__ b_conf){
    __shared__ __align__(16) float hn[DIM];
    const int tid = threadIdx.x;
    for (int j = tid; j < DIM; j += 256){
        float ihr = g_ihh[j],      ihz = g_ihh[512+j],  ihn = g_ihh[1024+j];
        float hhr = g_ihh[1536+j], hhz = g_ihh[2048+j], hhn = g_ihh[2560+j];
        float r = 1.0f/(1.0f + expf(-(ihr + hhr)));
        float z = 1.0f/(1.0f + expf(-(ihz + hhz)));
        float nn = tanhf(ihn + r*(hhn + b_hn[j]));
        float h = (1.0f - z)*nn + z*g_h[p][j];
        hn[j] = h;
        if (blockIdx.x == 0) g_h[1-p][j] = h;
    }
    __syncthreads();
    const int warp = tid >> 5, lane = tid & 31;
    const int gw = blockIdx.x*8 + warp;
    const float4* H4 = (const float4*)hn;
    float4 hv[4];
    #pragma unroll
    for (int k = 0; k < 4; k++) hv[k] = H4[lane + 32*k];
    #pragma unroll
    for (int rr = 0; rr < 2; rr++){
        int row = gw*2 + rr;
        const float4* W = (const float4*)(W_attr + (size_t)row*DIM);
        float a = 0.f;
        #pragma unroll
        for (int k = 0; k < 4; k++){
            float4 w = W[lane + 32*k];
            a += w.x*hv[k].x + w.y*hv[k].y + w.z*hv[k].z + w.w*hv[k].w;
        }
        a = wred(a);
        if (lane == 0){
            float v = a + b_attr[row];
            out[step*ATTR + row] = v;
            g_x[row] = v;
        }
    }
    if (gw == 0){
        const float4* W = (const float4*)W_conf;
        float a = 0.f;
        #pragma unroll
        for (int k = 0; k < 4; k++){
            float4 w = W[lane + 32*k];
            a += w.x*hv[k].x + w.y*hv[k].y + w.z*hv[k].z + w.w*hv[k].w;
        }
        a = wred(a);
        if (lane == 0)
            out[KSTEPS*ATTR + step] = 1.0f/(1.0f + expf(-(a + b_conf[0])));
    }
}

// ------------------------------- launch -----------------------------------
extern "C" void kernel_launch(void* const* d_in, const int* in_sizes, int n_in,
                              void* d_out, int out_size){
    const float* F      = (const float*)d_in[0];
    const float* Wctx   = (const float*)d_in[1];
    const float* bctx   = (const float*)d_in[2];
    const float* Wq     = (const float*)d_in[3];
    const float* bq     = (const float*)d_in[4];
    const float* Wk     = (const float*)d_in[5];
    // d_in[6] = bk : softmax-invariant, unused
    const float* Wv     = (const float*)d_in[7];
    const float* bv     = (const float*)d_in[8];
    const float* Wo     = (const float*)d_in[9];
    const float* bo     = (const float*)d_in[10];
    const float* W_ih   = (const float*)d_in[11];
    const float* W_hh   = (const float*)d_in[12];
    const float* b_ih   = (const float*)d_in[13];
    const float* b_hn   = (const float*)d_in[14];
    const float* start  = (const float*)d_in[15];
    const float* W_attr = (const float*)d_in[16];
    const float* b_attr = (const float*)d_in[17];
    const float* W_conf = (const float*)d_in[18];
    const float* b_conf = (const float*)d_in[19];
    float* out = (float*)d_out;

    p0_zero<<<1, 512>>>();
    p1c<<<128, 128>>>((const float4*)F);
    p1t<<<dim3(NFR/64, 8), 256>>>();
    p2_gemm<<<dim3(16,16,2), dim3(32,8)>>>(Wctx, Wk, Wv);
    p3_wih<<<dim3(12,24), 256>>>(W_ih, Wo);
    p4a<<<8, 256>>>(bctx, Wv, bv);
    p4b<<<8, 256>>>(Wo, bo);
    p4c<<<24, 256>>>(W_ih, b_ih, start);
    p4d<<<16, 256>>>(Wctx, bctx, bq);

    for (int step = 0; step < KSTEPS; step++){
        int p = step & 1;
        s1_u<<<8, 256>>>(Wq, p);
        sL<<<128, 256>>>();
        sW<<<GRIDW, 256>>>();
        s3c<<<16, 256>>>();
        s5_gru<<<96, 256>>>(W_hh, p);
        s6_fin<<<16, 256>>>(p, step, out, b_hn, W_attr, b_attr, W_conf, b_conf);
    }
}

// round 6
// speedup vs baseline: 1.8532x; 1.8532x over previous
#include <cuda_runtime.h>
#include <cuda_bf16.h>
#include <math.h>

#define NFR    65536
#define DIM    512
#define HEADS  8
#define ATTR   256
#define XDIM   768
#define KSTEPS 16
#define SCALE  0.125f
#define NSTREAM 296
#define GRIDA  148

// ------------------------- static device scratch -------------------------
__device__ __align__(16) __nv_bfloat16 g_Fh[NFR*DIM];    // bf16 frames (64MB)
__device__ __align__(16) float g_WckT[DIM*DIM];          // scale*(W_ctx@Wk)^T [o][i]
__device__ __align__(16) float g_Wcv [DIM*DIM];          // W_ctx@Wv [i][o]
__device__ __align__(16) float g_A[HEADS*DIM*DIM];       // A_h = WckT_h @ Wq_h^T (8MB)
__device__ __align__(16) float g_Wih2[1536*XDIM];        // [W_ih[:,:256] | W_ih[:,256:]@Wo^T]
__device__ __align__(16) float g_bih2[1536];
__device__ __align__(16) float g_cvec[HEADS*DIM];
__device__ __align__(16) float g_cspart[1024*DIM];       // per-block colsum partials
__device__ __align__(16) float g_colsum[DIM];
__device__ __align__(16) float g_h[2][DIM];
__device__ __align__(16) float g_u[HEADS*DIM];           // [h][i]
__device__ __align__(16) float g_x[XDIM];                // [a_prev(256); vraw(512)]
__device__ __align__(16) float g_ihh[3072];
__device__ __align__(16) float g_wpart[GRIDA*4096];      // per-block weighted sums
__device__ float g_spart[GRIDA*HEADS];
__device__ float g_mpart[GRIDA*HEADS];

__device__ __forceinline__ float wred(float a){
    #pragma unroll
    for (int o = 16; o; o >>= 1) a += __shfl_xor_sync(0xffffffffu, a, o);
    return a;
}
// ---- packed fp32 (f32x2) helpers ----
typedef unsigned long long ull;
#define FMA2(d,a,b) asm("fma.rn.f32x2 %0, %1, %2, %0;" : "+l"(d) : "l"(a), "l"(b))
#define MUL2(d,a,b) asm("mul.rn.f32x2 %0, %1, %2;" : "=l"(d) : "l"(a), "l"(b))
__device__ __forceinline__ ull fpack(float a, float b){
    ull r; asm("mov.b64 %0, {%1, %2};" : "=l"(r) : "f"(a), "f"(b)); return r;
}
__device__ __forceinline__ ull bfp(unsigned w){
    unsigned lo = w << 16, hi = w & 0xffff0000u;
    ull r; asm("mov.b64 %0, {%1, %2};" : "=l"(r) : "r"(lo), "r"(hi)); return r;
}
__device__ __forceinline__ float2 funp(ull v){
    float x, y; asm("mov.b64 {%0, %1}, %2;" : "=f"(x), "=f"(y) : "l"(v));
    return make_float2(x, y);
}

// ------------------------------ setup ------------------------------------
// F -> bf16 + per-block colsum partials. grid 1024 x 256.
__global__ void p1c(const float4* __restrict__ F4){
    const int tid = threadIdx.x, col = tid & 127, rh = tid >> 7;
    const int r0 = blockIdx.x*64;
    float4 acc = make_float4(0.f,0.f,0.f,0.f);
    uint2* out = (uint2*)g_Fh;
    for (int i = 0; i < 32; i++){
        size_t row = r0 + i*2 + rh;
        float4 f = F4[row*128 + col];
        acc.x += f.x; acc.y += f.y; acc.z += f.z; acc.w += f.w;
        uint2 pk;
        pk.x = ((unsigned)__bfloat16_as_ushort(__float2bfloat16_rn(f.y)) << 16)
             |  (unsigned)__bfloat16_as_ushort(__float2bfloat16_rn(f.x));
        pk.y = ((unsigned)__bfloat16_as_ushort(__float2bfloat16_rn(f.w)) << 16)
             |  (unsigned)__bfloat16_as_ushort(__float2bfloat16_rn(f.z));
        out[row*128 + col] = pk;
    }
    __shared__ float cs[512];
    if (rh == 0){
        cs[col*4+0]=acc.x; cs[col*4+1]=acc.y; cs[col*4+2]=acc.z; cs[col*4+3]=acc.w;
    }
    __syncthreads();
    if (rh == 1){
        size_t b = (size_t)blockIdx.x*512 + col*4;
        g_cspart[b+0] = cs[col*4+0]+acc.x;
        g_cspart[b+1] = cs[col*4+1]+acc.y;
        g_cspart[b+2] = cs[col*4+2]+acc.z;
        g_cspart[b+3] = cs[col*4+3]+acc.w;
    }
}

// z=0: WckT = scale*(W_ctx@Wk)^T ; z=1: Wcv = W_ctx@Wv ; z=2: colsum reduce
__global__ void p2(const float* __restrict__ Wctx,
                   const float* __restrict__ Wk,
                   const float* __restrict__ Wv){
    if (blockIdx.z == 2){
        if (blockIdx.y != 0) return;
        const int tid = threadIdx.y*32 + threadIdx.x;
        const int col = blockIdx.x*32 + (tid & 31), seg = tid >> 5;
        float a = 0.f;
        #pragma unroll 8
        for (int p = seg*128; p < seg*128+128; p++) a += g_cspart[(size_t)p*512 + col];
        __shared__ float sr[8][33];
        sr[seg][tid & 31] = a;
        __syncthreads();
        if (tid < 32){
            float s2 = 0.f;
            #pragma unroll
            for (int q = 0; q < 8; q++) s2 += sr[q][tid];
            g_colsum[blockIdx.x*32 + tid] = s2;
        }
        return;
    }
    __shared__ float sA[32][33];
    __shared__ float sB[32][33];
    int tx = threadIdx.x, ty = threadIdx.y;
    const float* B = blockIdx.z ? Wv : Wk;
    int i0 = blockIdx.y*32, j0 = blockIdx.x*32;
    float acc[4] = {0.f,0.f,0.f,0.f};
    for (int m0 = 0; m0 < DIM; m0 += 32){
        #pragma unroll
        for (int k = 0; k < 4; k++){
            sA[ty+8*k][tx] = Wctx[(size_t)(i0+ty+8*k)*DIM + m0+tx];
            sB[ty+8*k][tx] = B[(size_t)(m0+ty+8*k)*DIM + j0+tx];
        }
        __syncthreads();
        #pragma unroll
        for (int mm = 0; mm < 32; mm++){
            float b = sB[mm][tx];
            #pragma unroll
            for (int k = 0; k < 4; k++) acc[k] += sA[ty+8*k][mm]*b;
        }
        __syncthreads();
    }
    if (blockIdx.z){
        #pragma unroll
        for (int k = 0; k < 4; k++)
            g_Wcv[(size_t)(i0+ty+8*k)*DIM + j0+tx] = acc[k];
    } else {
        __syncthreads();
        #pragma unroll
        for (int k = 0; k < 4; k++) sA[tx][ty+8*k] = acc[k];
        __syncthreads();
        #pragma unroll
        for (int k = 0; k < 4; k++)
            g_WckT[(size_t)(j0+ty+8*k)*DIM + i0+tx] = SCALE*sA[ty+8*k][tx];
    }
}

// z<8: A_h[i][j] = sum_d WckT[h*64+d][i]*Wq[j][h*64+d]  (scale already in WckT)
// z=8: Wih2 build (gemm x<8, copy x in 8..11)
__global__ __launch_bounds__(256) void pAB(const float* __restrict__ Wq,
                                           const float* __restrict__ W_ih,
                                           const float* __restrict__ Wo){
    const int tid = threadIdx.x;
    const int z = blockIdx.z;
    if (z < 8){
        if (blockIdx.y >= 16) return;
        __shared__ float sA_[32][65];
        __shared__ float sB_[32][65];
        const int h = z, i0 = blockIdx.y*32, j0 = blockIdx.x*32;
        for (int e = tid; e < 2048; e += 256){
            int r = e & 31, d = e >> 5;
            sA_[r][d] = g_WckT[(size_t)(h*64+d)*DIM + i0 + r];
        }
        for (int e = tid; e < 2048; e += 256){
            int rj = e >> 6, d = e & 63;
            sB_[rj][d] = Wq[(size_t)(j0+rj)*DIM + h*64 + d];
        }
        __syncthreads();
        const int tx = tid & 31, ty = tid >> 5;
        float acc[4] = {0.f,0.f,0.f,0.f};
        #pragma unroll 8
        for (int d = 0; d < 64; d++){
            float bb = sB_[tx][d];
            #pragma unroll
            for (int k = 0; k < 4; k++) acc[k] += sA_[ty+8*k][d]*bb;
        }
        #pragma unroll
        for (int k = 0; k < 4; k++)
            g_A[(size_t)(h*DIM + i0+ty+8*k)*DIM + j0+tx] = acc[k];
    } else {
        const int i0 = blockIdx.y*64;
        if (blockIdx.x < 8){
            __shared__ float sA[64][33];
            __shared__ float sB[64][33];
            const int j0 = blockIdx.x*64;
            const int tx = tid & 15, ty = tid >> 4;
            float acc[4][4];
            #pragma unroll
            for (int a = 0; a < 4; a++)
                #pragma unroll
                for (int b = 0; b < 4; b++) acc[a][b] = 0.f;
            for (int m0 = 0; m0 < DIM; m0 += 32){
                #pragma unroll
                for (int q = 0; q < 2; q++){
                    int e = tid + q*256, r = e >> 3, c = e & 7;
                    float4 va = *(const float4*)(W_ih + (size_t)(i0+r)*XDIM + 256 + m0 + c*4);
                    sA[r][c*4+0]=va.x; sA[r][c*4+1]=va.y; sA[r][c*4+2]=va.z; sA[r][c*4+3]=va.w;
                    float4 vb = *(const float4*)(Wo + (size_t)(j0+r)*DIM + m0 + c*4);
                    sB[r][c*4+0]=vb.x; sB[r][c*4+1]=vb.y; sB[r][c*4+2]=vb.z; sB[r][c*4+3]=vb.w;
                }
                __syncthreads();
                #pragma unroll
                for (int m = 0; m < 32; m++){
                    float a4[4], b4[4];
                    #pragma unroll
                    for (int k = 0; k < 4; k++){ a4[k] = sA[ty*4+k][m]; b4[k] = sB[tx*4+k][m]; }
                    #pragma unroll
                    for (int a = 0; a < 4; a++)
                        #pragma unroll
                        for (int b = 0; b < 4; b++) acc[a][b] += a4[a]*b4[b];
                }
                __syncthreads();
            }
            #pragma unroll
            for (int a = 0; a < 4; a++){
                float4 v = make_float4(acc[a][0], acc[a][1], acc[a][2], acc[a][3]);
                *(float4*)(g_Wih2 + (size_t)(i0+ty*4+a)*XDIM + 256 + j0 + tx*4) = v;
            }
        } else if (blockIdx.x < 12){
            const int c0 = (blockIdx.x-8)*64;
            for (int e = tid; e < 64*16; e += 256){
                int r = e >> 4, c = e & 15;
                *(float4*)(g_Wih2 + (size_t)(i0+r)*XDIM + c0 + c*4) =
                    *(const float4*)(W_ih + (size_t)(i0+r)*XDIM + c0 + c*4);
            }
        }
    }
}

// vectors: h0 (b<8), cvec (b<16), bih2 (b<40), start copy (b=40)
__global__ void p4(const float* __restrict__ Wctx, const float* __restrict__ bctx,
                   const float* __restrict__ bq,   const float* __restrict__ Wv,
                   const float* __restrict__ bv,   const float* __restrict__ bo,
                   const float* __restrict__ W_ih, const float* __restrict__ b_ih,
                   const float* __restrict__ start){
    const int b = blockIdx.x, tid = threadIdx.x;
    if (b < 8){
        __shared__ float sp[4][64];
        const int tc = tid & 63, pc = tid >> 6;
        const int t = b*64 + tc;
        float a = 0.f;
        #pragma unroll 4
        for (int i = pc*128; i < pc*128+128; i++) a += g_colsum[i]*Wctx[(size_t)i*DIM + t];
        sp[pc][tc] = a;
        __syncthreads();
        if (tid < 64)
            g_h[0][b*64+tid] = (sp[0][tid]+sp[1][tid]+sp[2][tid]+sp[3][tid])*(1.0f/(float)NFR)
                               + bctx[b*64+tid];
    } else if (b < 16){
        const int h = b - 8;
        #pragma unroll
        for (int rr = 0; rr < 2; rr++){
            int i = rr*256 + tid;
            float s = 0.f;
            #pragma unroll 8
            for (int d = 0; d < 64; d++)
                s += g_WckT[(size_t)(h*64+d)*DIM + i]*bq[h*64+d];
            g_cvec[h*DIM + i] = s;
        }
    } else if (b < 40){
        __shared__ float sbvp[DIM];
        __shared__ float sbo[DIM];
        #pragma unroll
        for (int rr = 0; rr < 2; rr++){
            int t = rr*256 + tid;
            float a = bv[t];
            #pragma unroll 8
            for (int i = 0; i < DIM; i++) a += bctx[i]*Wv[(size_t)i*DIM + t];
            sbvp[t] = a;
            sbo[t] = bo[t];
        }
        __syncthreads();
        const int w = tid >> 5, lane = tid & 31;
        const int r0 = (b-16)*64;
        for (int rr = w; rr < 64; rr += 8){
            int r = r0 + rr;
            const float4* W2 = (const float4*)(g_Wih2 + (size_t)r*XDIM + 256);
            const float4* WI = (const float4*)(W_ih + (size_t)r*XDIM + 256);
            float a = 0.f;
            #pragma unroll
            for (int k = 0; k < 4; k++){
                float4 w2 = W2[lane+32*k];
                float4 wi = WI[lane+32*k];
                int kb = (lane+32*k)*4;
                a += w2.x*sbvp[kb+0] + w2.y*sbvp[kb+1] + w2.z*sbvp[kb+2] + w2.w*sbvp[kb+3];
                a += wi.x*sbo[kb+0]  + wi.y*sbo[kb+1]  + wi.z*sbo[kb+2]  + wi.w*sbo[kb+3];
            }
            a = wred(a);
            if (lane == 0) g_bih2[r] = a + b_ih[r];
        }
    } else {
        if (tid < ATTR) g_x[tid] = start[tid];
    }
}

// ----------------------------- per-step ----------------------------------
// u = A@h + cvec ; block 0 zeroes vraw. grid 128 x 256.
__global__ void s1_u(int p){
    const int tid = threadIdx.x, w = tid >> 5, lane = tid & 31;
    if (blockIdx.x == 0){ g_x[256+tid] = 0.f; g_x[512+tid] = 0.f; }
    const float4* H4 = (const float4*)g_h[p];
    float4 hv[4];
    #pragma unroll
    for (int k = 0; k < 4; k++) hv[k] = H4[lane + 32*k];
    const int gw = blockIdx.x*8 + w;
    #pragma unroll
    for (int rr = 0; rr < 4; rr++){
        int r = gw + rr*1024;
        const float4* A4 = (const float4*)(g_A + (size_t)r*DIM);
        float a = 0.f;
        #pragma unroll
        for (int k = 0; k < 4; k++){
            float4 av = A4[lane + 32*k];
            a += av.x*hv[k].x + av.y*hv[k].y + av.z*hv[k].z + av.w*hv[k].w;
        }
        a = wred(a);
        if (lane == 0) g_u[r] = a + g_cvec[r];
    }
}

// Fused single-pass flash attention. grid 148 x 512. warp = head, 8 warps/row-stream.
__global__ void __launch_bounds__(512,1) sA(){
    const int tid = threadIdx.x, w = tid >> 5, lane = tid & 31;
    const int head = w & 7, grp = w >> 3;
    const int stream = blockIdx.x*2 + grp;          // 0..295

    // u for this head, lane chunk: k in {8*lane + 256*jj .. +8}
    ull u[8];
    {
        const float4* U4 = (const float4*)(g_u + head*DIM);
        #pragma unroll
        for (int jj = 0; jj < 2; jj++){
            float4 va = U4[2*lane + 64*jj];
            float4 vb = U4[2*lane + 64*jj + 1];
            u[4*jj+0] = fpack(va.x, va.y);
            u[4*jj+1] = fpack(va.z, va.w);
            u[4*jj+2] = fpack(vb.x, vb.y);
            u[4*jj+3] = fpack(vb.z, vb.w);
        }
    }
    ull acc[8];
    #pragma unroll
    for (int j = 0; j < 8; j++) acc[j] = 0ull;
    float m = -3.0e38f, s = 0.f;

    const uint4* Fq = (const uint4*)g_Fh;
    int n = stream;
    uint4 ra = Fq[(size_t)n*64 + lane];
    uint4 rb = Fq[(size_t)n*64 + lane + 32];
    for (;;){
        int nn = n + NSTREAM;
        bool more = nn < NFR;
        uint4 na, nb;
        if (more){
            size_t rq = (size_t)nn*64;
            na = Fq[rq + lane]; nb = Fq[rq + lane + 32];
        }
        ull f0 = bfp(ra.x), f1 = bfp(ra.y), f2 = bfp(ra.z), f3 = bfp(ra.w);
        ull f4 = bfp(rb.x), f5 = bfp(rb.y), f6 = bfp(rb.z), f7 = bfp(rb.w);
        ull l0 = 0ull, l1 = 0ull;
        FMA2(l0, f0, u[0]); FMA2(l1, f1, u[1]);
        FMA2(l0, f2, u[2]); FMA2(l1, f3, u[3]);
        FMA2(l0, f4, u[4]); FMA2(l1, f5, u[5]);
        FMA2(l0, f6, u[6]); FMA2(l1, f7, u[7]);
        float2 pa = funp(l0), pb = funp(l1);
        float l = (pa.x + pb.x) + (pa.y + pb.y);
        l = wred(l);                               // warp-uniform logit
        if (l > m){                                // warp-uniform branch
            float sc = __expf(m - l);
            s *= sc;
            ull scp = fpack(sc, sc);
            #pragma unroll
            for (int j = 0; j < 8; j++) MUL2(acc[j], acc[j], scp);
            m = l;
        }
        float e = __expf(l - m);
        s += e;
        ull ee = fpack(e, e);
        FMA2(acc[0], ee, f0); FMA2(acc[1], ee, f1);
        FMA2(acc[2], ee, f2); FMA2(acc[3], ee, f3);
        FMA2(acc[4], ee, f4); FMA2(acc[5], ee, f5);
        FMA2(acc[6], ee, f6); FMA2(acc[7], ee, f7);
        if (!more) break;
        n = nn; ra = na; rb = nb;
    }

    // pair-combine (warp w with w+8, same head) and emit block partials
    __shared__ float sm_[16], ss_[16];
    __shared__ __align__(16) float sacc[16*512];
    if (lane == 0){ sm_[w] = m; ss_[w] = s; }
    float* base = sacc + w*512;
    #pragma unroll
    for (int jj = 0; jj < 2; jj++){
        float2 v0 = funp(acc[4*jj+0]), v1 = funp(acc[4*jj+1]);
        float2 v2 = funp(acc[4*jj+2]), v3 = funp(acc[4*jj+3]);
        *(float4*)&base[8*lane + 256*jj]     = make_float4(v0.x, v0.y, v1.x, v1.y);
        *(float4*)&base[8*lane + 256*jj + 4] = make_float4(v2.x, v2.y, v3.x, v3.y);
    }
    __syncthreads();
    if (w < 8){
        float m1 = sm_[w], m2 = sm_[w+8];
        float M = fmaxf(m1, m2);
        float c1 = __expf(m1 - M), c2 = __expf(m2 - M);
        const float* b1 = sacc + w*512;
        const float* b2 = sacc + (w+8)*512;
        float* op = g_wpart + (size_t)blockIdx.x*4096 + w*512;
        #pragma unroll
        for (int t = lane*4; t < 512; t += 128){
            float4 x1 = *(const float4*)&b1[t];
            float4 x2 = *(const float4*)&b2[t];
            float4 o = make_float4(x1.x*c1 + x2.x*c2, x1.y*c1 + x2.y*c2,
                                   x1.z*c1 + x2.z*c2, x1.w*c1 + x2.w*c2);
            *(float4*)&op[t] = o;
        }
        if (lane == 0){
            g_spart[blockIdx.x*8 + w] = ss_[w]*c1 + ss_[w+8]*c2;
            g_mpart[blockIdx.x*8 + w] = M;
        }
    }
}

// combine partials (exact m-realign) -> c ; vraw += c@Wcv. grid 16 x 256.
__global__ void s3c(){
    __shared__ float sef[GRIDA*8];
    __shared__ float sM[8], sS[8];
    __shared__ float scv[256];
    __shared__ float sv[4][64];
    const int tid = threadIdx.x, bi = blockIdx.x;
    for (int i = tid; i < GRIDA*8; i += 256) sef[i] = g_mpart[i];
    __syncthreads();
    if (tid < 8){
        float M = -3.0e38f;
        for (int b = 0; b < GRIDA; b++) M = fmaxf(M, sef[b*8+tid]);
        sM[tid] = M;
    }
    __syncthreads();
    for (int i = tid; i < GRIDA*8; i += 256) sef[i] = __expf(sef[i] - sM[i&7]);
    __syncthreads();
    if (tid < 8){
        float S = 0.f;
        for (int b = 0; b < GRIDA; b++) S += g_spart[b*8+tid]*sef[b*8+tid];
        sS[tid] = S;
    }
    __syncthreads();
    const int idx = bi*256 + tid;
    const int hb = bi >> 1;
    {
        float a = 0.f;
        #pragma unroll 8
        for (int b = 0; b < GRIDA; b++) a += g_wpart[(size_t)b*4096 + idx]*sef[b*8+hb];
        scv[tid] = a / sS[hb];
    }
    __syncthreads();
    const int d = tid & 63, isub = tid >> 6;
    const int i0 = (bi & 1)*256;
    float pv = 0.f;
    #pragma unroll 8
    for (int ii = 0; ii < 64; ii++){
        int i = i0 + isub*64 + ii;
        pv += scv[isub*64+ii]*g_Wcv[(size_t)i*DIM + hb*64 + d];
    }
    sv[isub][d] = pv;
    __syncthreads();
    if (tid < 64)
        atomicAdd(&g_x[256 + hb*64 + tid],
                  sv[0][tid]+sv[1][tid]+sv[2][tid]+sv[3][tid]);
}

// GRU matvecs
__global__ void s5_gru(const float* __restrict__ W_hh, int p){
    const int warp = threadIdx.x >> 5, lane = threadIdx.x & 31;
    const int gw = blockIdx.x*8 + warp, nw = gridDim.x*8;
    for (int r = gw; r < 3072; r += nw){
        float a = 0.f;
        if (r < 1536){
            const float4* W = (const float4*)(g_Wih2 + (size_t)r*XDIM);
            const float4* X = (const float4*)g_x;
            #pragma unroll
            for (int k = 0; k < 6; k++){
                float4 w = W[lane + 32*k], x = X[lane + 32*k];
                a += w.x*x.x + w.y*x.y + w.z*x.z + w.w*x.w;
            }
            a = wred(a);
            if (lane == 0) g_ihh[r] = a + g_bih2[r];
        } else {
            int rr = r - 1536;
            const float4* W = (const float4*)(W_hh + (size_t)rr*DIM);
            const float4* H = (const float4*)g_h[p];
            #pragma unroll
            for (int k = 0; k < 4; k++){
                float4 w = W[lane + 32*k], h = H[lane + 32*k];
                a += w.x*h.x + w.y*h.y + w.z*h.z + w.w*h.w;
            }
            a = wred(a);
            if (lane == 0) g_ihh[r] = a;
        }
    }
}

// gates + heads + output
__global__ void s6_fin(int p, int step, float* __restrict__ out,
                       const float* __restrict__ b_hn,
                       const float* __restrict__ W_attr, const float* __restrict__ b_attr,
                       const float* __restrict__ W_conf, const float* __restrict__ b_conf){
    __shared__ __align__(16) float hn[DIM];
    const int tid = threadIdx.x;
    for (int j = tid; j < DIM; j += 256){
        float ihr = g_ihh[j],      ihz = g_ihh[512+j],  ihn = g_ihh[1024+j];
        float hhr = g_ihh[1536+j], hhz = g_ihh[2048+j], hhn = g_ihh[2560+j];
        float r = 1.0f/(1.0f + expf(-(ihr + hhr)));
        float z = 1.0f/(1.0f + expf(-(ihz + hhz)));
        float nn = tanhf(ihn + r*(hhn + b_hn[j]));
        float h = (1.0f - z)*nn + z*g_h[p][j];
        hn[j] = h;
        if (blockIdx.x == 0) g_h[1-p][j] = h;
    }
    __syncthreads();
    const int warp = tid >> 5, lane = tid & 31;
    const int gw = blockIdx.x*8 + warp;
    const float4* H4 = (const float4*)hn;
    float4 hv[4];
    #pragma unroll
    for (int k = 0; k < 4; k++) hv[k] = H4[lane + 32*k];
    #pragma unroll
    for (int rr = 0; rr < 2; rr++){
        int row = gw*2 + rr;
        const float4* W = (const float4*)(W_attr + (size_t)row*DIM);
        float a = 0.f;
        #pragma unroll
        for (int k = 0; k < 4; k++){
            float4 w = W[lane + 32*k];
            a += w.x*hv[k].x + w.y*hv[k].y + w.z*hv[k].z + w.w*hv[k].w;
        }
        a = wred(a);
        if (lane == 0){
            float v = a + b_attr[row];
            out[step*ATTR + row] = v;
            g_x[row] = v;
        }
    }
    if (gw == 0){
        const float4* W = (const float4*)W_conf;
        float a = 0.f;
        #pragma unroll
        for (int k = 0; k < 4; k++){
            float4 w = W[lane + 32*k];
            a += w.x*hv[k].x + w.y*hv[k].y + w.z*hv[k].z + w.w*hv[k].w;
        }
        a = wred(a);
        if (lane == 0)
            out[KSTEPS*ATTR + step] = 1.0f/(1.0f + expf(-(a + b_conf[0])));
    }
}

// ------------------------------- launch -----------------------------------
extern "C" void kernel_launch(void* const* d_in, const int* in_sizes, int n_in,
                              void* d_out, int out_size){
    const float* F      = (const float*)d_in[0];
    const float* Wctx   = (const float*)d_in[1];
    const float* bctx   = (const float*)d_in[2];
    const float* Wq     = (const float*)d_in[3];
    const float* bq     = (const float*)d_in[4];
    const float* Wk     = (const float*)d_in[5];
    // d_in[6] = bk : softmax-invariant, unused
    const float* Wv     = (const float*)d_in[7];
    const float* bv     = (const float*)d_in[8];
    const float* Wo     = (const float*)d_in[9];
    const float* bo     = (const float*)d_in[10];
    const float* W_ih   = (const float*)d_in[11];
    const float* W_hh   = (const float*)d_in[12];
    const float* b_ih   = (const float*)d_in[13];
    const float* b_hn   = (const float*)d_in[14];
    const float* start  = (const float*)d_in[15];
    const float* W_attr = (const float*)d_in[16];
    const float* b_attr = (const float*)d_in[17];
    const float* W_conf = (const float*)d_in[18];
    const float* b_conf = (const float*)d_in[19];
    float* out = (float*)d_out;

    p1c<<<1024, 256>>>((const float4*)F);                 // launch 0
    p2 <<<dim3(16,16,3), dim3(32,8)>>>(Wctx, Wk, Wv);     // launch 1
    pAB<<<dim3(16,24,9), 256>>>(Wq, W_ih, Wo);            // launch 2
    p4 <<<41, 256>>>(Wctx, bctx, bq, Wv, bv, bo, W_ih, b_ih, start);  // launch 3

    for (int step = 0; step < KSTEPS; step++){
        int p = step & 1;
        s1_u<<<128, 256>>>(p);                            // launch 4 (step 0)
        sA  <<<GRIDA, 512>>>();                           // launch 5 (step 0) -> ncu target
        s3c <<<16, 256>>>();
        s5_gru<<<96, 256>>>(W_hh, p);
        s6_fin<<<16, 256>>>(p, step, out, b_hn, W_attr, b_attr, W_conf, b_conf);
    }
}